// round 4
// baseline (speedup 1.0000x reference)
#include <cuda_runtime.h>
#include <cstdint>

#define BB   4096
#define TT   288
#define HIDN 64
#define GG   256
#define NB   8            // batches per CTA; 512 CTAs exactly covers 4096
#define NTH  256
#define EPSF 1e-5f

__device__ float g_inv_den[TT];

typedef unsigned long long u64;

__device__ __forceinline__ u64 pack2(float a, float b) {
    u64 r; asm("mov.b64 %0, {%1, %2};" : "=l"(r) : "f"(a), "f"(b)); return r;
}
__device__ __forceinline__ u64 ffma2(u64 a, u64 b, u64 c) {
    u64 d; asm("fma.rn.f32x2 %0, %1, %2, %3;" : "=l"(d) : "l"(a), "l"(b), "l"(c)); return d;
}
__device__ __forceinline__ u64 fadd2(u64 a, u64 b) {
    u64 d; asm("add.rn.f32x2 %0, %1, %2;" : "=l"(d) : "l"(a), "l"(b)); return d;
}
__device__ __forceinline__ float2 unpk(u64 a) {
    float2 f; asm("mov.b64 {%0, %1}, %2;" : "=f"(f.x), "=f"(f.y) : "l"(a)); return f;
}
__device__ __forceinline__ float fast_rcp(float x) {
    float r; asm("rcp.approx.f32 %0, %1;" : "=f"(r) : "f"(x)); return r;
}
__device__ __forceinline__ float fast_ex2(float x) {
    float r; asm("ex2.approx.f32 %0, %1;" : "=f"(r) : "f"(x)); return r;
}
__device__ __forceinline__ float sigf(float x) {
    return fast_rcp(1.f + fast_ex2(-1.4426950408889634f * x));
}
__device__ __forceinline__ float tanhfast(float x) {
    // tanh(x) = 1 - 2/(1+e^{2x})
    return fmaf(-2.f, fast_rcp(1.f + fast_ex2(2.8853900817779268f * x)), 1.f);
}
__device__ __forceinline__ float expneg(float x) {   // exp(-relu(x))
    return fast_ex2(-1.4426950408889634f * fmaxf(x, 0.f));
}
__device__ __forceinline__ float clipf(float v, float lo, float hi) {
    return fminf(fmaxf(v, lo), hi);
}
// Two independent butterfly reductions, interleaved so the SHFL latencies of
// the a- and b-chains overlap.
__device__ __forceinline__ void warp_red2(float& a, float& b) {
#pragma unroll
    for (int o = 16; o > 0; o >>= 1) {
        float ta = __shfl_xor_sync(0xffffffffu, a, o);
        float tb = __shfl_xor_sync(0xffffffffu, b, o);
        a += ta;
        b += tb;
    }
}
__device__ __forceinline__ uint32_t smem_u32(const void* p) {
    return (uint32_t)__cvta_generic_to_shared(p);
}
__device__ __forceinline__ void cpa4(void* dst, const void* src) {
    asm volatile("cp.async.ca.shared.global [%0], [%1], 4;" :: "r"(smem_u32(dst)), "l"(src));
}
__device__ __forceinline__ void cpa8(void* dst, const void* src) {
    asm volatile("cp.async.ca.shared.global [%0], [%1], 8;" :: "r"(smem_u32(dst)), "l"(src));
}
#define CP_COMMIT() asm volatile("cp.async.commit_group;" ::: "memory")
#define CP_WAIT0()  asm volatile("cp.async.wait_group 0;" ::: "memory")

// ---------------------------------------------------------------------------
// Kernel A: per-timestep mask denominator.
// ---------------------------------------------------------------------------
__global__ void den_kernel(const float* __restrict__ masks, float* __restrict__ out) {
    __shared__ float red[256];
    const int t = blockIdx.x;
    float s = 0.f;
    for (int b = threadIdx.x; b < BB; b += 256) {
        const float* p = masks + ((size_t)b * TT + t) * 2;
        s += p[0] + p[1];
    }
    red[threadIdx.x] = s;
    __syncthreads();
    for (int o = 128; o > 0; o >>= 1) {
        if (threadIdx.x < o) red[threadIdx.x] += red[threadIdx.x + o];
        __syncthreads();
    }
    if (threadIdx.x == 0) {
        g_inv_den[t] = __fdividef(1.f, red[0] + EPSF);
        if (t == 0) out[0] = 0.f;
    }
}

// ---------------------------------------------------------------------------
// Kernel B: persistent recurrent kernel. 512 CTAs x 256 threads, 8 batches
// per CTA (warp w owns batch w for scalar chain + LSTM pointwise).
// Thread = one gate row (W_hh[row] packed f32x2 in registers).
// ---------------------------------------------------------------------------
__global__ void __launch_bounds__(NTH, 3) rnn_kernel(
    const float* __restrict__ Xg,  const float* __restrict__ XOg,
    const float* __restrict__ Mg,  const float* __restrict__ Dg,
    const float* __restrict__ MAXSR, const float* __restrict__ SRMEAN,
    const float* __restrict__ SRSTD,
    const float* __restrict__ Wgh, const float* __restrict__ Bgh,
    const float* __restrict__ Wgx, const float* __restrict__ Bgx,
    const float* __restrict__ Whist, const float* __restrict__ Bhist,
    const float* __restrict__ Wfr, const float* __restrict__ Bfr,
    const float* __restrict__ Wwc, const float* __restrict__ Bwc,
    const float* __restrict__ Wih, const float* __restrict__ Whh,
    const float* __restrict__ Bih, const float* __restrict__ Bhh,
    float* __restrict__ out)
{
    __shared__ __align__(16) float h_sm[NB][HIDN];
    __shared__ float  gates_sm[NB][GG];
    __shared__ __align__(16) float4 inp_sm[NB];
    __shared__ __align__(16) float xb[2][NB][2], mb[2][NB][2], db[2][NB][2];
    __shared__ __align__(16) float xob[2][NB][32];
    __shared__ float  invden_sm[TT];
    __shared__ float  loss_sm[NB];
    // small weights in smem to relieve register pressure
    __shared__ float  wgh0s[HIDN], wgh1s[HIDN], bghs[HIDN];
    __shared__ float  wh0s[HIDN], wh1s[HIDN];
    __shared__ float  wfr0s[32], wfr1s[32];
    __shared__ __align__(16) float wih_s[GG][4];
    __shared__ float  biasg_s[GG];
    __shared__ float  K[24];
    // K: 0 bh0 1 bh1 2 bfr0 3 bfr1 4 bwc0 5 bwc1 6 wgx0 7 wgx1 8 bgx0 9 bgx1
    //    10..17 wc00..wc13  18 ub0 19 ub1 20 lb0 21 lb1  22 wfr0e 23 wfr1e

    const int bstart = blockIdx.x * NB;
    const int tid = threadIdx.x;
    const int w = tid >> 5, l = tid & 31;

    // ---- gate-row weights (registers, f32x2 packed) ----
    u64 whh2[32];
    {
        const float4* wr = reinterpret_cast<const float4*>(Whh + tid * HIDN);
#pragma unroll
        for (int k = 0; k < 16; k++) {
            float4 v = wr[k];
            whh2[2 * k]     = pack2(v.x, v.y);
            whh2[2 * k + 1] = pack2(v.z, v.w);
        }
    }

    // ---- fill shared constant tables ----
    if (tid < HIDN) {
        wgh0s[tid] = Wgh[tid * 2];
        wgh1s[tid] = Wgh[tid * 2 + 1];
        bghs[tid]  = Bgh[tid];
        wh0s[tid]  = Whist[tid];
        wh1s[tid]  = Whist[HIDN + tid];
    }
    if (tid < 32) {
        wfr0s[tid] = (tid == 0) ? 0.f : Wfr[tid];
        wfr1s[tid] = (tid == 1) ? 0.f : Wfr[33 + tid];
    }
    {
        float4 wv = *reinterpret_cast<const float4*>(Wih + tid * 4);
        *reinterpret_cast<float4*>(wih_s[tid]) = wv;
        biasg_s[tid] = Bih[tid] + Bhh[tid];
    }
    if (tid == 0) {
        K[0] = Bhist[0]; K[1] = Bhist[1]; K[2] = Bfr[0]; K[3] = Bfr[1];
        K[4] = Bwc[0];   K[5] = Bwc[1];
        K[6] = Wgx[0];   K[7] = Wgx[3];   K[8] = Bgx[0]; K[9] = Bgx[1];
        K[10] = Wwc[0];  K[11] = Wwc[1];  K[12] = Wwc[2]; K[13] = Wwc[3];
        K[14] = Wwc[4];  K[15] = Wwc[5];  K[16] = Wwc[6]; K[17] = Wwc[7];
        K[18] = (1.5f * MAXSR[0] - SRMEAN[0]) / SRSTD[0];
        K[19] = (1.5f * MAXSR[1] - SRMEAN[1]) / SRSTD[1];
        K[20] = (0.f - SRMEAN[0]) / SRSTD[0];
        K[21] = (0.f - SRMEAN[1]) / SRSTD[1];
        K[22] = Wfr[32]; K[23] = Wfr[33 + 32];
    }
    for (int i = tid; i < TT; i += NTH) invden_sm[i] = g_inv_den[i];
    for (int i = tid; i < NB * HIDN; i += NTH) (&h_sm[0][0])[i] = 0.f;

    // ---- cp.async loader: warp w loads batch w, lane-sliced ----
    const size_t bg = (size_t)(bstart + w);
    const float* xBase  = Xg  + bg * TT * 2;
    const float* mBase  = Mg  + bg * TT * 2;
    const float* dBase  = Dg  + bg * TT * 2;
    const float* xoBase = XOg + bg * TT * 31;
    auto issue = [&](int t, int pb) {
        if (l == 0)       cpa8(&xb[pb][w][0], xBase + (size_t)t * 2);
        else if (l == 1) { cpa8(&mb[pb][w][0], mBase + (size_t)t * 2);
                           cpa4(&xob[pb][w][29], xoBase + (size_t)t * 31 + 29); }
        else if (l == 2) { cpa8(&db[pb][w][0], dBase + (size_t)t * 2);
                           cpa4(&xob[pb][w][30], xoBase + (size_t)t * 31 + 30); }
        else              cpa4(&xob[pb][w][l - 3], xoBase + (size_t)t * 31 + (l - 3));
    };

    float cA = 0.f, cB = 0.f, lossAcc = 0.f;
    const int jA = l, jB = l + 32;

    issue(0, 0);
    CP_COMMIT();
    CP_WAIT0();
    __syncthreads();

    for (int t = 0; t < TT; t++) {
        const int pb = t & 1;

        // ================= stage 1: scalar chain, warp w -> batch w ==========
        {
            const float x0 = xb[pb][w][0], x1 = xb[pb][w][1];
            const float m0 = mb[pb][w][0], m1 = mb[pb][w][1];
            const float d0 = db[pb][w][0], d1 = db[pb][w][1];

            float ga = expneg(fmaf(d1, wgh1s[jA], fmaf(d0, wgh0s[jA], bghs[jA])));
            float gb = expneg(fmaf(d1, wgh1s[jB], fmaf(d0, wgh0s[jB], bghs[jB])));
            float hA = h_sm[w][jA] * ga;
            float hB = h_sm[w][jB] * gb;
            h_sm[w][jA] = hA;
            h_sm[w][jB] = hB;

            float p0 = hA * wh0s[jA] + hB * wh0s[jB];
            float p1 = hA * wh1s[jA] + hB * wh1s[jB];
            warp_red2(p0, p1);
            const float ub0 = K[18], ub1 = K[19], lb0 = K[20], lb1 = K[21];
            float xh0 = clipf(p0 + K[0], lb0, ub0);
            float xh1 = clipf(p1 + K[1], lb1, ub1);
            float lnum = fabsf(x0 - xh0) * m0 + fabsf(x1 - xh1) * m1;
            float xc0 = m0 * x0 + (1.f - m0) * xh0;
            float xc1 = m1 * x1 + (1.f - m1) * xh1;

            float vl = (l == 0) ? xc0 : (l == 1) ? xc1 : xob[pb][w][l - 2];
            float q0 = wfr0s[l] * vl;
            float q1 = wfr1s[l] * vl;
            if (l == 0) {
                float xo30 = xob[pb][w][30];
                q0 = fmaf(K[22], xo30, q0);
                q1 = fmaf(K[23], xo30, q1);
            }
            warp_red2(q0, q1);
            float zh0 = clipf(q0 + K[2], lb0, ub0);
            float zh1 = clipf(q1 + K[3], lb1, ub1);
            lnum += fabsf(x0 - zh0) * m0 + fabsf(x1 - zh1) * m1;

            float gx0 = expneg(fmaf(d0, K[6], K[8]));
            float gx1 = expneg(fmaf(d1, K[7], K[9]));
            float a0 = K[4] + K[10] * gx0 + K[11] * gx1 + K[12] * m0 + K[13] * m1;
            float a1 = K[5] + K[14] * gx0 + K[15] * gx1 + K[16] * m0 + K[17] * m1;
            float ch0 = clipf(a0 * zh0 + (1.f - a0) * xh0, lb0, ub0);
            float ch1 = clipf(a1 * zh1 + (1.f - a1) * xh1, lb1, ub1);
            lnum += fabsf(x0 - ch0) * m0 + fabsf(x1 - ch1) * m1;
            float cc0 = m0 * x0 + (1.f - m0) * ch0;
            float cc1 = m1 * x1 + (1.f - m1) * ch1;
            lossAcc += lnum * invden_sm[t];
            if (l == 0) {
                inp_sm[w] = make_float4(cc0, cc1, m0, m1);
                float* op = out + 1 + (bg * TT + (size_t)t) * 2;
                op[0] = cc0;
                op[1] = cc1;
            }
        }
        __syncthreads();

        // ================= stage 2: gate GEMV (f32x2) + t+1 prefetch =========
        if (t + 1 < TT) issue(t + 1, pb ^ 1);
        CP_COMMIT();
        // hoist per-row constants out of the unrolled bb loop
        const float4 wv = *reinterpret_cast<const float4*>(wih_s[tid]);
        const float  bgr = biasg_s[tid];
#pragma unroll
        for (int bb = 0; bb < NB; bb++) {
            const ulonglong2* h4 = reinterpret_cast<const ulonglong2*>(h_sm[bb]);
            u64 a0 = 0, a1 = 0, a2 = 0, a3 = 0;
#pragma unroll
            for (int k = 0; k < 8; k++) {
                ulonglong2 hv = h4[2 * k];
                ulonglong2 hw = h4[2 * k + 1];
                a0 = ffma2(whh2[4 * k + 0], hv.x, a0);
                a1 = ffma2(whh2[4 * k + 1], hv.y, a1);
                a2 = ffma2(whh2[4 * k + 2], hw.x, a2);
                a3 = ffma2(whh2[4 * k + 3], hw.y, a3);
            }
            float2 s = unpk(fadd2(fadd2(a0, a1), fadd2(a2, a3)));
            float4 inp = inp_sm[bb];
            float g = s.x + s.y + bgr
                    + wv.x * inp.x + wv.y * inp.y + wv.z * inp.z + wv.w * inp.w;
            gates_sm[bb][tid] = g;
        }
        CP_WAIT0();
        __syncthreads();

        // ================= stage 3: LSTM pointwise, warp w -> batch w ========
        {
            float gi = gates_sm[w][jA],       gf = gates_sm[w][jA + 64];
            float gc = gates_sm[w][jA + 128], go = gates_sm[w][jA + 192];
            cA = sigf(gf) * cA + sigf(gi) * tanhfast(gc);
            h_sm[w][jA] = sigf(go) * tanhfast(cA);
            gi = gates_sm[w][jB];       gf = gates_sm[w][jB + 64];
            gc = gates_sm[w][jB + 128]; go = gates_sm[w][jB + 192];
            cB = sigf(gf) * cB + sigf(gi) * tanhfast(gc);
            h_sm[w][jB] = sigf(go) * tanhfast(cB);
        }
        // stage3's h writes are consumed first by the same warp's stage1,
        // then published to other warps by the stage1-end barrier.
    }

    if (l == 0) loss_sm[w] = lossAcc;
    __syncthreads();
    if (tid == 0) {
        float s = 0.f;
#pragma unroll
        for (int i = 0; i < NB; i++) s += loss_sm[i];
        atomicAdd(out, s);
    }
}

// ---------------------------------------------------------------------------
extern "C" void kernel_launch(void* const* d_in, const int* in_sizes, int n_in,
                              void* d_out, int out_size) {
    const float* X     = (const float*)d_in[0];
    const float* XO    = (const float*)d_in[1];
    const float* M     = (const float*)d_in[2];
    const float* D     = (const float*)d_in[3];
    const float* MAXSR = (const float*)d_in[4];
    const float* SRM   = (const float*)d_in[5];
    const float* SRS   = (const float*)d_in[6];
    const float* Wgh   = (const float*)d_in[7];
    const float* Bgh   = (const float*)d_in[8];
    const float* Wgx   = (const float*)d_in[9];
    const float* Bgx   = (const float*)d_in[10];
    const float* Whist = (const float*)d_in[11];
    const float* Bhist = (const float*)d_in[12];
    const float* Wfr   = (const float*)d_in[13];
    const float* Bfr   = (const float*)d_in[14];
    const float* Wwc   = (const float*)d_in[15];
    const float* Bwc   = (const float*)d_in[16];
    const float* Wih   = (const float*)d_in[17];
    const float* Whh   = (const float*)d_in[18];
    const float* Bih   = (const float*)d_in[19];
    const float* Bhh   = (const float*)d_in[20];
    float* out = (float*)d_out;

    den_kernel<<<TT, 256>>>(M, out);
    rnn_kernel<<<BB / NB, NTH>>>(X, XO, M, D, MAXSR, SRM, SRS,
                                 Wgh, Bgh, Wgx, Bgx, Whist, Bhist,
                                 Wfr, Bfr, Wwc, Bwc, Wih, Whh, Bih, Bhh, out);
}